// round 6
// baseline (speedup 1.0000x reference)
#include <cuda_runtime.h>
#include <cstdint>

#define SAMPLE 8192
#define KNN 8
#define NQ 4            // queries per warp
#define WPB 4           // warps per block
#define CAP 768         // survivor buffer per query (u32 indices)
#define SUB 512         // threshold subsample size
#define EPSV 1e-12f
#define SENT 0x7F800000FFFFFFFFull
#define FINF __int_as_float(0x7f800000)

// g_P: (x, y, z, |p|^2) query side.
// g_Q: (-2x, -2y, -2z, |p|^2) candidate side: d2 = (wi+wj) + dot(q,p).
__device__ float4 g_P[SAMPLE];
__device__ float4 g_Q[SAMPLE];
__device__ float4 g_S[SAMPLE];

__global__ void gather_kernel(const float* __restrict__ means,
                              const float* __restrict__ sh0,
                              const int* __restrict__ idx_raw,
                              float* __restrict__ out) {
    int i = blockIdx.x * blockDim.x + threadIdx.x;
    if (i == 0) *out = 0.f;  // fold the memset in (same stream, ordered)
    if (i >= SAMPLE) return;
    // Detect int64 vs int32 index layout: little-endian int64 values < 2^31
    // have all odd int32 words zero.
    bool is64 = ((idx_raw[1] | idx_raw[3] | idx_raw[5] | idx_raw[7] |
                  idx_raw[9] | idx_raw[11] | idx_raw[13] | idx_raw[15]) == 0);
    long long j = is64 ? ((const long long*)idx_raw)[i] : (long long)idx_raw[i];
    float x = means[3 * j + 0];
    float y = means[3 * j + 1];
    float z = means[3 * j + 2];
    float sq = fmaf(z, z, fmaf(y, y, x * x));
    g_P[i] = make_float4(x, y, z, sq);
    g_Q[i] = make_float4(-2.f * x, -2.f * y, -2.f * z, sq);
    g_S[i] = make_float4(sh0[3 * j + 0], sh0[3 * j + 1], sh0[3 * j + 2], 0.f);
}

__device__ __forceinline__ void insert9(unsigned long long heap[9],
                                        unsigned long long key) {
    unsigned long long cur = key;  // flat if-converted insert (rare paths only)
#pragma unroll
    for (int k = 0; k < 9; k++) {
        unsigned long long h = heap[k];
        bool lt = cur < h;
        heap[k] = lt ? cur : h;
        cur = lt ? h : cur;
    }
}

// 128 threads = 4 warps; each warp owns NQ=4 queries; block shares cand tiles.
__global__ void __launch_bounds__(128) knn_loss_kernel(float* __restrict__ out) {
    __shared__ float4 tile[256];
    __shared__ unsigned buf[WPB][NQ][CAP];
    __shared__ unsigned cnt[WPB][NQ];

    const int lane = threadIdx.x & 31;
    const int warp = threadIdx.x >> 5;
    const int qbase = (blockIdx.x * WPB + warp) * NQ;

    if (threadIdx.x < WPB * NQ) ((unsigned*)cnt)[threadIdx.x] = 0;

    float4 pis[NQ];
#pragma unroll
    for (int q = 0; q < NQ; q++) pis[q] = g_P[qbase + q];

    // ---- Phase 1: per-query value threshold T[q] = (approx) 9th-smallest
    // clamped d2 over the first SUB candidates. A subset's 9th order stat
    // bounds the full set's from above, so filtering d2 <= T[q] keeps every
    // true top-9 member. Float-only insert (no index) — ties and multi-pop
    // in the merge only make T looser, never invalid.
    float T[NQ];
#pragma unroll
    for (int q = 0; q < NQ; q++) {
        float fh[9];
#pragma unroll
        for (int k = 0; k < 9; k++) fh[k] = FINF;
#pragma unroll 4
        for (int u = 0; u < SUB / 32; u++) {
            float4 c = g_Q[u * 32 + lane];
            float d2 = c.w + pis[q].w;
            d2 = fmaf(c.x, pis[q].x, d2);
            d2 = fmaf(c.y, pis[q].y, d2);
            d2 = fmaf(c.z, pis[q].z, d2);
            float cur = fmaxf(d2, EPSV);
#pragma unroll
            for (int k = 0; k < 9; k++) {
                float h = fh[k];
                bool lt = cur < h;
                fh[k] = lt ? cur : h;
                cur = lt ? h : cur;
            }
        }
        float Tq = FINF;
#pragma unroll
        for (int r = 0; r < 9; r++) {
            float cand = fh[0];
            float m = cand;
#pragma unroll
            for (int o = 16; o > 0; o >>= 1)
                m = fminf(m, __shfl_xor_sync(0xFFFFFFFFu, m, o));
            if (cand == m) {  // equal-value heads pop together: T only loosens
#pragma unroll
                for (int k = 0; k < 8; k++) fh[k] = fh[k + 1];
                fh[8] = FINF;
            }
            if (r == 8) Tq = m;
        }
        T[q] = Tq;
    }

    // ---- Phase 2: full scan; block-shared tiles; buffer surviving indices.
    // Raw d2 <= clamped d2, so comparing raw vs T is safe (no false reject).
#pragma unroll 1
    for (int t = 0; t < SAMPLE; t += 256) {
        __syncthreads();
        tile[threadIdx.x] = g_Q[t + threadIdx.x];
        tile[threadIdx.x + 128] = g_Q[t + threadIdx.x + 128];
        __syncthreads();
#pragma unroll
        for (int u = 0; u < 8; u++) {
            float4 c = tile[u * 32 + lane];
            float d0 = c.w + pis[0].w, d1 = c.w + pis[1].w;
            float d2_ = c.w + pis[2].w, d3 = c.w + pis[3].w;
            d0 = fmaf(c.x, pis[0].x, d0);
            d1 = fmaf(c.x, pis[1].x, d1);
            d2_ = fmaf(c.x, pis[2].x, d2_);
            d3 = fmaf(c.x, pis[3].x, d3);
            d0 = fmaf(c.y, pis[0].y, d0);
            d1 = fmaf(c.y, pis[1].y, d1);
            d2_ = fmaf(c.y, pis[2].y, d2_);
            d3 = fmaf(c.y, pis[3].y, d3);
            d0 = fmaf(c.z, pis[0].z, d0);
            d1 = fmaf(c.z, pis[1].z, d1);
            d2_ = fmaf(c.z, pis[2].z, d2_);
            d3 = fmaf(c.z, pis[3].z, d3);
            bool a0 = d0 <= T[0], a1 = d1 <= T[1];
            bool a2 = d2_ <= T[2], a3 = d3 <= T[3];
            if (a0 | a1 | a2 | a3) {  // contains atomics -> real branch
                unsigned j = (unsigned)(t + u * 32 + lane);
                if (a0) {
                    unsigned s = atomicAdd(&cnt[warp][0], 1u);
                    if (s < CAP) buf[warp][0][s] = j;
                }
                if (a1) {
                    unsigned s = atomicAdd(&cnt[warp][1], 1u);
                    if (s < CAP) buf[warp][1][s] = j;
                }
                if (a2) {
                    unsigned s = atomicAdd(&cnt[warp][2], 1u);
                    if (s < CAP) buf[warp][2][s] = j;
                }
                if (a3) {
                    unsigned s = atomicAdd(&cnt[warp][3], 1u);
                    if (s < CAP) buf[warp][3][s] = j;
                }
            }
        }
    }
    __syncthreads();

    // ---- Phase 3: exact (d2,j)-keyed top-9 over survivors, per query.
    float acc = 0.f;
#pragma unroll 1
    for (int q = 0; q < NQ; q++) {
        float4 pq = g_P[qbase + q];
        unsigned long long heap[9];
#pragma unroll
        for (int k = 0; k < 9; k++) heap[k] = SENT;
        unsigned n = cnt[warp][q];
        if (n > CAP) n = CAP;
        for (unsigned s = lane; s < n; s += 32) {
            unsigned j = buf[warp][q][s];
            float4 c = g_Q[j];
            float d2 = c.w + pq.w;
            d2 = fmaf(c.x, pq.x, d2);
            d2 = fmaf(c.y, pq.y, d2);
            d2 = fmaf(c.z, pq.z, d2);
            float d2c = fmaxf(d2, EPSV);
            insert9(heap, ((unsigned long long)__float_as_uint(d2c) << 32) | j);
        }
        // Warp pop-merge: >=9 real keys exist (subsample top-9 all pass T),
        // real u64 keys unique (distinct j) -> exactly one lane pops/round.
        unsigned long long mykey = SENT;
#pragma unroll
        for (int r = 0; r < 9; r++) {
            unsigned long long cand = heap[0];
            unsigned long long m = cand;
#pragma unroll
            for (int o = 16; o > 0; o >>= 1) {
                unsigned long long other = __shfl_xor_sync(0xFFFFFFFFu, m, o);
                m = (other < m) ? other : m;
            }
            if (cand == m) {
#pragma unroll
                for (int k = 0; k < 8; k++) heap[k] = heap[k + 1];
                heap[8] = SENT;
            }
            if (lane == r) mykey = m;
        }
        // Ranks 1..8 (rank 0 = self/dup, dropped like knn_idx[:, 1:])
        if (lane >= 1 && lane <= KNN) {
            int j = (int)(mykey & 0xFFFFFFFFu);
            float d2 = __uint_as_float((unsigned)(mykey >> 32));
            float w = __expf(-sqrtf(d2));
            float4 si = g_S[qbase + q];
            float4 sj = g_S[j];
            float dx = si.x - sj.x, dy = si.y - sj.y, dz = si.z - sj.z;
            acc += w * (dx * dx + dy * dy + dz * dz);
        }
    }
#pragma unroll
    for (int o = 16; o > 0; o >>= 1)
        acc += __shfl_xor_sync(0xFFFFFFFFu, acc, o);
    if (lane == 0)
        atomicAdd(out, acc * (1.f / (float)(SAMPLE * KNN * 3)));
}

extern "C" void kernel_launch(void* const* d_in, const int* in_sizes, int n_in,
                              void* d_out, int out_size) {
    const float* means = (const float*)d_in[0];
    const float* sh0 = (const float*)d_in[1];
    const int* idx = (const int*)d_in[2];
    float* out = (float*)d_out;

    gather_kernel<<<SAMPLE / 256, 256>>>(means, sh0, idx, out);
    knn_loss_kernel<<<SAMPLE / (WPB * NQ), 128>>>(out);
}

// round 7
// speedup vs baseline: 1.3000x; 1.3000x over previous
#include <cuda_runtime.h>
#include <cstdint>

#define SAMPLE 8192
#define KNN 8
#define NQ 2            // queries per warp
#define WPB 4           // warps per block
#define CAP 768         // survivor buffer per query (u16 indices)
#define SUB 512         // threshold subsample size
#define EPSV 1e-12f
#define SENT 0x7F800000FFFFFFFFull
#define FINF __int_as_float(0x7f800000)

// g_P: (x, y, z, |p|^2) query side.
// g_Q: (-2x, -2y, -2z, |p|^2) candidate side: d2 = (wi+wj) + dot(q,p).
// g_QP: pair-interleaved candidate layout, 2 float4 per candidate pair:
//   [2p]   = (-2x_{2p}, -2x_{2p+1}, -2y_{2p}, -2y_{2p+1})
//   [2p+1] = (-2z_{2p}, -2z_{2p+1},  w_{2p},   w_{2p+1})
__device__ float4 g_P[SAMPLE];
__device__ float4 g_Q[SAMPLE];
__device__ float4 g_QP[SAMPLE];
__device__ float4 g_S[SAMPLE];

__device__ __forceinline__ unsigned long long pk2(float lo, float hi) {
    unsigned long long r;
    asm("mov.b64 %0, {%1, %2};" : "=l"(r) : "f"(lo), "f"(hi));
    return r;
}
__device__ __forceinline__ unsigned long long add2(unsigned long long a,
                                                   unsigned long long b) {
    unsigned long long r;
    asm("add.rn.f32x2 %0, %1, %2;" : "=l"(r) : "l"(a), "l"(b));
    return r;
}
__device__ __forceinline__ unsigned long long fma2(unsigned long long a,
                                                   unsigned long long b,
                                                   unsigned long long c) {
    unsigned long long r;
    asm("fma.rn.f32x2 %0, %1, %2, %3;" : "=l"(r) : "l"(a), "l"(b), "l"(c));
    return r;
}
__device__ __forceinline__ void upk2(unsigned long long v, float& lo, float& hi) {
    asm("mov.b64 {%0, %1}, %2;" : "=f"(lo), "=f"(hi) : "l"(v));
}

__global__ void gather_kernel(const float* __restrict__ means,
                              const float* __restrict__ sh0,
                              const int* __restrict__ idx_raw,
                              float* __restrict__ out) {
    int i = blockIdx.x * blockDim.x + threadIdx.x;
    if (i == 0) *out = 0.f;
    if (i >= SAMPLE) return;
    // int64 vs int32 index detection: little-endian int64 < 2^31 has all odd
    // words zero.
    bool is64 = ((idx_raw[1] | idx_raw[3] | idx_raw[5] | idx_raw[7] |
                  idx_raw[9] | idx_raw[11] | idx_raw[13] | idx_raw[15]) == 0);
    long long j = is64 ? ((const long long*)idx_raw)[i] : (long long)idx_raw[i];
    float x = means[3 * j + 0];
    float y = means[3 * j + 1];
    float z = means[3 * j + 2];
    float sq = fmaf(z, z, fmaf(y, y, x * x));
    g_P[i] = make_float4(x, y, z, sq);
    g_Q[i] = make_float4(-2.f * x, -2.f * y, -2.f * z, sq);
    g_S[i] = make_float4(sh0[3 * j + 0], sh0[3 * j + 1], sh0[3 * j + 2], 0.f);
    // pair-interleaved writes
    float* qp = (float*)g_QP;
    int p = i >> 1, o = i & 1;
    qp[p * 8 + 0 + o] = -2.f * x;
    qp[p * 8 + 2 + o] = -2.f * y;
    qp[p * 8 + 4 + o] = -2.f * z;
    qp[p * 8 + 6 + o] = sq;
}

__device__ __forceinline__ void insert9(unsigned long long heap[9],
                                        unsigned long long key) {
    unsigned long long cur = key;  // flat if-converted insert (rare paths)
#pragma unroll
    for (int k = 0; k < 9; k++) {
        unsigned long long h = heap[k];
        bool lt = cur < h;
        heap[k] = lt ? cur : h;
        cur = lt ? h : cur;
    }
}

// 128 threads = 4 warps; each warp owns NQ=2 queries; block shares cand tiles.
__global__ void __launch_bounds__(128) knn_loss_kernel(float* __restrict__ out) {
    __shared__ float4 tile[256];
    __shared__ unsigned short buf[WPB][NQ][CAP];

    const int lane = threadIdx.x & 31;
    const int warp = threadIdx.x >> 5;
    const int qbase = (blockIdx.x * WPB + warp) * NQ;
    const unsigned ltmask = (1u << lane) - 1u;

    const float4 pi0 = g_P[qbase + 0];
    const float4 pi1 = g_P[qbase + 1];

    // ---- Phase 1: per-query threshold T = 9th-smallest clamped d2 over the
    // first SUB candidates (subset order stat >= full-set order stat, so
    // d2 <= T keeps every true top-9 member).
    float fh0[9], fh1[9];
#pragma unroll
    for (int k = 0; k < 9; k++) { fh0[k] = FINF; fh1[k] = FINF; }
#pragma unroll 4
    for (int u = 0; u < SUB / 32; u++) {
        float4 c = g_Q[u * 32 + lane];
        float d0 = c.w + pi0.w;
        d0 = fmaf(c.x, pi0.x, d0);
        d0 = fmaf(c.y, pi0.y, d0);
        d0 = fmaf(c.z, pi0.z, d0);
        float cur0 = fmaxf(d0, EPSV);
        float d1 = c.w + pi1.w;
        d1 = fmaf(c.x, pi1.x, d1);
        d1 = fmaf(c.y, pi1.y, d1);
        d1 = fmaf(c.z, pi1.z, d1);
        float cur1 = fmaxf(d1, EPSV);
#pragma unroll
        for (int k = 0; k < 9; k++) {
            float h0 = fh0[k];
            fh0[k] = fminf(cur0, h0);
            cur0 = fmaxf(cur0, h0);
            float h1 = fh1[k];
            fh1[k] = fminf(cur1, h1);
            cur1 = fmaxf(cur1, h1);
        }
    }
    float T0 = FINF, T1 = FINF;
#pragma unroll
    for (int r = 0; r < 9; r++) {
        float c0 = fh0[0], m0 = c0;
        float c1 = fh1[0], m1 = c1;
#pragma unroll
        for (int o = 16; o > 0; o >>= 1) {
            m0 = fminf(m0, __shfl_xor_sync(0xFFFFFFFFu, m0, o));
            m1 = fminf(m1, __shfl_xor_sync(0xFFFFFFFFu, m1, o));
        }
        if (c0 == m0) {  // equal heads pop together: T only loosens (still valid)
#pragma unroll
            for (int k = 0; k < 8; k++) fh0[k] = fh0[k + 1];
            fh0[8] = FINF;
        }
        if (c1 == m1) {
#pragma unroll
            for (int k = 0; k < 8; k++) fh1[k] = fh1[k + 1];
            fh1[8] = FINF;
        }
        if (r == 8) { T0 = m0; T1 = m1; }
    }

    // Packed query broadcasts for the f32x2 scan.
    const unsigned long long PX0 = pk2(pi0.x, pi0.x), PY0 = pk2(pi0.y, pi0.y);
    const unsigned long long PZ0 = pk2(pi0.z, pi0.z), PW0 = pk2(pi0.w, pi0.w);
    const unsigned long long PX1 = pk2(pi1.x, pi1.x), PY1 = pk2(pi1.y, pi1.y);
    const unsigned long long PZ1 = pk2(pi1.z, pi1.z), PW1 = pk2(pi1.w, pi1.w);

    unsigned cnt0 = 0, cnt1 = 0;  // warp-uniform survivor counts

    // ---- Phase 2: full scan, 2 candidates x 2 queries per lane-iter.
    // Packed fma.rn.f32x2 is per-lane IEEE rn with the same op order as the
    // scalar chain in phases 1/3, so the filter is bitwise-consistent.
#pragma unroll 1
    for (int t = 0; t < SAMPLE; t += 256) {
        __syncthreads();
        tile[threadIdx.x] = g_QP[t + threadIdx.x];
        tile[threadIdx.x + 128] = g_QP[t + threadIdx.x + 128];
        __syncthreads();
#pragma unroll
        for (int u = 0; u < 4; u++) {
            int p = u * 32 + lane;  // local pair index
            float4 A = tile[2 * p];      // (xa,xb,ya,yb)
            float4 B = tile[2 * p + 1];  // (za,zb,wa,wb)
            unsigned long long xv = pk2(A.x, A.y), yv = pk2(A.z, A.w);
            unsigned long long zv = pk2(B.x, B.y), wv = pk2(B.z, B.w);
            unsigned long long dq0 = add2(wv, PW0);
            dq0 = fma2(xv, PX0, dq0);
            dq0 = fma2(yv, PY0, dq0);
            dq0 = fma2(zv, PZ0, dq0);
            unsigned long long dq1 = add2(wv, PW1);
            dq1 = fma2(xv, PX1, dq1);
            dq1 = fma2(yv, PY1, dq1);
            dq1 = fma2(zv, PZ1, dq1);
            float d0a, d0b, d1a, d1b;
            upk2(dq0, d0a, d0b);
            upk2(dq1, d1a, d1b);
            unsigned jlo = (unsigned)(t + 2 * p);
            // Per-query warp-uniform branch (vote cannot be if-converted).
            if (__any_sync(0xFFFFFFFFu, fminf(d0a, d0b) <= T0)) {
                bool aa = d0a <= T0, ab = d0b <= T0;
                unsigned ma = __ballot_sync(0xFFFFFFFFu, aa);
                unsigned mb = __ballot_sync(0xFFFFFFFFu, ab);
                unsigned base_b = cnt0 + __popc(ma);
                if (aa) {
                    unsigned s = cnt0 + __popc(ma & ltmask);
                    if (s < CAP) buf[warp][0][s] = (unsigned short)jlo;
                }
                if (ab) {
                    unsigned s = base_b + __popc(mb & ltmask);
                    if (s < CAP) buf[warp][0][s] = (unsigned short)(jlo + 1);
                }
                cnt0 = base_b + __popc(mb);
            }
            if (__any_sync(0xFFFFFFFFu, fminf(d1a, d1b) <= T1)) {
                bool aa = d1a <= T1, ab = d1b <= T1;
                unsigned ma = __ballot_sync(0xFFFFFFFFu, aa);
                unsigned mb = __ballot_sync(0xFFFFFFFFu, ab);
                unsigned base_b = cnt1 + __popc(ma);
                if (aa) {
                    unsigned s = cnt1 + __popc(ma & ltmask);
                    if (s < CAP) buf[warp][1][s] = (unsigned short)jlo;
                }
                if (ab) {
                    unsigned s = base_b + __popc(mb & ltmask);
                    if (s < CAP) buf[warp][1][s] = (unsigned short)(jlo + 1);
                }
                cnt1 = base_b + __popc(mb);
            }
        }
    }
    __syncwarp();

    // ---- Phase 3: exact (d2,j)-keyed top-9 over survivors, per query.
    float acc = 0.f;
#pragma unroll 1
    for (int q = 0; q < NQ; q++) {
        float4 pq = (q == 0) ? pi0 : pi1;
        unsigned n = (q == 0) ? cnt0 : cnt1;
        if (n > CAP) n = CAP;
        unsigned long long heap[9];
#pragma unroll
        for (int k = 0; k < 9; k++) heap[k] = SENT;
        for (unsigned s = lane; s < n; s += 32) {
            unsigned j = buf[warp][q][s];
            float4 c = g_Q[j];
            float d2 = c.w + pq.w;
            d2 = fmaf(c.x, pq.x, d2);
            d2 = fmaf(c.y, pq.y, d2);
            d2 = fmaf(c.z, pq.z, d2);
            float d2c = fmaxf(d2, EPSV);
            insert9(heap, ((unsigned long long)__float_as_uint(d2c) << 32) | j);
        }
        // Pop-merge: >=9 real keys (subsample top-9 all pass T), keys unique
        // (distinct j) -> exactly one lane pops per round.
        unsigned long long mykey = SENT;
#pragma unroll
        for (int r = 0; r < 9; r++) {
            unsigned long long cand = heap[0];
            unsigned long long m = cand;
#pragma unroll
            for (int o = 16; o > 0; o >>= 1) {
                unsigned long long other = __shfl_xor_sync(0xFFFFFFFFu, m, o);
                m = (other < m) ? other : m;
            }
            if (cand == m) {
#pragma unroll
                for (int k = 0; k < 8; k++) heap[k] = heap[k + 1];
                heap[8] = SENT;
            }
            if (lane == r) mykey = m;
        }
        // Ranks 1..8 (rank 0 = self/dup, dropped like knn_idx[:, 1:])
        if (lane >= 1 && lane <= KNN) {
            int j = (int)(mykey & 0xFFFFFFFFu);
            float d2 = __uint_as_float((unsigned)(mykey >> 32));
            float w = __expf(-sqrtf(d2));
            float4 si = g_S[qbase + q];
            float4 sj = g_S[j];
            float dx = si.x - sj.x, dy = si.y - sj.y, dz = si.z - sj.z;
            acc += w * (dx * dx + dy * dy + dz * dz);
        }
    }
#pragma unroll
    for (int o = 16; o > 0; o >>= 1)
        acc += __shfl_xor_sync(0xFFFFFFFFu, acc, o);
    if (lane == 0)
        atomicAdd(out, acc * (1.f / (float)(SAMPLE * KNN * 3)));
}

extern "C" void kernel_launch(void* const* d_in, const int* in_sizes, int n_in,
                              void* d_out, int out_size) {
    const float* means = (const float*)d_in[0];
    const float* sh0 = (const float*)d_in[1];
    const int* idx = (const int*)d_in[2];
    float* out = (float*)d_out;

    gather_kernel<<<SAMPLE / 256, 256>>>(means, sh0, idx, out);
    knn_loss_kernel<<<SAMPLE / (WPB * NQ), 128>>>(out);
}